// round 1
// baseline (speedup 1.0000x reference)
#include <cuda_runtime.h>
#include <cuda_bf16.h>
#include <cstdint>

#define BB 512
#define DD 256
#define PP 196
#define NCA 8
#define SPITCH 264   // padded bf16 row pitch (528B) -> conflict-free ldmatrix

// ---------------- scratch (static device arrays; no allocation) ----------------
__device__ __nv_bfloat16 g_hat[(size_t)PP * BB * DD];   // normalized softmax^p(g)
__device__ __nv_bfloat16 lf_hat[(size_t)PP * BB * DD];  // normalized softmax(local)
__device__ float outT[(size_t)PP * BB * DD];            // outputs transposed [p][b][d]
__device__ float d_pos[(size_t)PP * BB];
__device__ float rowA_g[(size_t)PP * BB];
__device__ float rowB_g[(size_t)PP * BB];
__device__ float rowC_g[(size_t)PP * BB];
__device__ float colB_g[(size_t)PP * 4 * BB];           // per-strip col partials of Bm
__device__ float w_g[PP];
__device__ float part_g[PP];

// ---------------- helpers ----------------
__device__ __forceinline__ uint32_t smem_u32(const void* p) {
    return (uint32_t)__cvta_generic_to_shared(p);
}
__device__ __forceinline__ void ldsm_x4(uint32_t& r0, uint32_t& r1, uint32_t& r2,
                                        uint32_t& r3, uint32_t addr) {
    asm volatile("ldmatrix.sync.aligned.m8n8.x4.shared.b16 {%0,%1,%2,%3}, [%4];\n"
                 : "=r"(r0), "=r"(r1), "=r"(r2), "=r"(r3)
                 : "r"(addr));
}
__device__ __forceinline__ void mma16816(float* c, const uint32_t* a, const uint32_t* b) {
    asm volatile(
        "mma.sync.aligned.m16n8k16.row.col.f32.bf16.bf16.f32 "
        "{%0,%1,%2,%3}, {%4,%5,%6,%7}, {%8,%9}, {%0,%1,%2,%3};\n"
        : "+f"(c[0]), "+f"(c[1]), "+f"(c[2]), "+f"(c[3])
        : "r"(a[0]), "r"(a[1]), "r"(a[2]), "r"(a[3]), "r"(b[0]), "r"(b[1]));
}

// ---------------- kernel 1: repeated-softmax chain on global feature ----------------
// 512 independent rows; warp per row; lane holds 8 elements.
__global__ void g_chain_kernel(const float* __restrict__ g0) {
    int warp = threadIdx.x >> 5, lane = threadIdx.x & 31;
    int b = blockIdx.x * 8 + warp;
    float v[8];
#pragma unroll
    for (int r = 0; r < 8; r++) v[r] = g0[b * DD + r * 32 + lane];
    for (int p = 0; p < PP; p++) {
        float m = v[0];
#pragma unroll
        for (int r = 1; r < 8; r++) m = fmaxf(m, v[r]);
#pragma unroll
        for (int s = 16; s > 0; s >>= 1) m = fmaxf(m, __shfl_xor_sync(0xffffffffu, m, s));
        float s = 0.f;
#pragma unroll
        for (int r = 0; r < 8; r++) { v[r] = __expf(v[r] - m); s += v[r]; }
#pragma unroll
        for (int t = 16; t > 0; t >>= 1) s += __shfl_xor_sync(0xffffffffu, s, t);
        float inv = 1.f / s;
        float sq = 0.f;
#pragma unroll
        for (int r = 0; r < 8; r++) { v[r] *= inv; sq += v[r] * v[r]; }
#pragma unroll
        for (int t = 16; t > 0; t >>= 1) sq += __shfl_xor_sync(0xffffffffu, sq, t);
        float sc = 1.f / (sqrtf(sq) + 1e-8f);
        __nv_bfloat16* dst = &g_hat[((size_t)p * BB + b) * DD];
#pragma unroll
        for (int r = 0; r < 8; r++) dst[r * 32 + lane] = __float2bfloat16(v[r] * sc);
    }
}

// ---------------- kernel 2: transpose outputs [b][d][p] -> outT [p][b][d] ----------------
__global__ void transpose_kernel(const float* __restrict__ outp) {
    __shared__ float tile[32][33];
    int b = blockIdx.z;
    int p0 = blockIdx.x * 32, d0 = blockIdx.y * 32;
    int tx = threadIdx.x, ty = threadIdx.y;
#pragma unroll
    for (int yy = ty; yy < 32; yy += 8) {
        int p = p0 + tx;
        if (p < PP) tile[yy][tx] = outp[((size_t)b * DD + d0 + yy) * PP + p];
    }
    __syncthreads();
#pragma unroll
    for (int yy = ty; yy < 32; yy += 8) {
        int p = p0 + yy;
        if (p < PP) outT[((size_t)p * BB + b) * DD + d0 + tx] = tile[tx][yy];
    }
}

// ---------------- kernel 3: local softmax + normalize + positive dot ----------------
__global__ void lf_prep_kernel() {
    int warp = threadIdx.x >> 5, lane = threadIdx.x & 31;
    int p = blockIdx.x;
    int b = blockIdx.y * 8 + warp;
    const float* src = &outT[((size_t)p * BB + b) * DD];
    float v[8];
#pragma unroll
    for (int r = 0; r < 8; r++) v[r] = src[r * 32 + lane];
    float m = v[0];
#pragma unroll
    for (int r = 1; r < 8; r++) m = fmaxf(m, v[r]);
#pragma unroll
    for (int s = 16; s > 0; s >>= 1) m = fmaxf(m, __shfl_xor_sync(0xffffffffu, m, s));
    float s = 0.f;
#pragma unroll
    for (int r = 0; r < 8; r++) { v[r] = __expf(v[r] - m); s += v[r]; }
#pragma unroll
    for (int t = 16; t > 0; t >>= 1) s += __shfl_xor_sync(0xffffffffu, s, t);
    float inv = 1.f / s;
    float sq = 0.f;
#pragma unroll
    for (int r = 0; r < 8; r++) { v[r] *= inv; sq += v[r] * v[r]; }
#pragma unroll
    for (int t = 16; t > 0; t >>= 1) sq += __shfl_xor_sync(0xffffffffu, sq, t);
    float sc = 1.f / (sqrtf(sq) + 1e-8f);
    const __nv_bfloat16* gp = &g_hat[((size_t)p * BB + b) * DD];
    __nv_bfloat16* dst = &lf_hat[((size_t)p * BB + b) * DD];
    float dot = 0.f;
#pragma unroll
    for (int r = 0; r < 8; r++) {
        float z = v[r] * sc;
        dst[r * 32 + lane] = __float2bfloat16(z);
        dot += z * __bfloat162float(gp[r * 32 + lane]);
    }
#pragma unroll
    for (int t = 16; t > 0; t >>= 1) dot += __shfl_xor_sync(0xffffffffu, dot, t);
    if (lane == 0) d_pos[(size_t)p * BB + b] = 2.f * dot;
}

// ---------------- kernel 4: attention weights ----------------
__global__ void wmean_kernel(const float* __restrict__ att) {
    __shared__ float red[8];
    int p = blockIdx.x, tid = threadIdx.x;
    float s = 0.f;
    for (int i = tid; i < BB * NCA; i += 256) s += att[(size_t)i * PP + p];
    int lane = tid & 31, warp = tid >> 5;
#pragma unroll
    for (int t = 16; t > 0; t >>= 1) s += __shfl_xor_sync(0xffffffffu, s, t);
    if (lane == 0) red[warp] = s;
    __syncthreads();
    if (warp == 0) {
        s = (lane < 8) ? red[lane] : 0.f;
#pragma unroll
        for (int t = 4; t > 0; t >>= 1) s += __shfl_xor_sync(0xffffffffu, s, t);
        if (lane == 0) w_g[p] = s * (1.f / (512.f * 196.f));
    }
}

// ---------------- kernel 5: fused bf16 MMA Gram + exp row/col sums ----------------
// grid (strip=4, mat=3, p=196); block 256 threads (8 warps, 2x4 warp grid),
// block tile = 128 rows x 128 cols per chunk, 4 col-chunks cover 512 cols.
__global__ void __launch_bounds__(256, 1) gemm_kernel() {
    extern __shared__ __align__(16) __nv_bfloat16 smem[];
    __nv_bfloat16* sA = smem;                    // 128 x SPITCH
    __nv_bfloat16* sB = smem + 128 * SPITCH;     // 128 x SPITCH
    __shared__ float rowsum_s[128];
    __shared__ float colsum_s[512];

    int strip = blockIdx.x, mat = blockIdx.y, p = blockIdx.z;
    int tid = threadIdx.x, lane = tid & 31, warp = tid >> 5;
    int warpM = warp & 1, warpN = warp >> 1;
    const __nv_bfloat16* left = (mat == 2) ? g_hat : lf_hat;
    const __nv_bfloat16* right = (mat == 0) ? lf_hat : g_hat;
    const __nv_bfloat16* lsrc = left + ((size_t)p * BB + strip * 128) * DD;

    if (tid < 128) rowsum_s[tid] = 0.f;
    colsum_s[tid] = 0.f;
    colsum_s[tid + 256] = 0.f;

    // load A (row strip, full K) into smem
    for (int i = tid; i < 128 * 32; i += 256) {
        int r = i >> 5, c = i & 31;
        const int4 vv = *(const int4*)(lsrc + (size_t)r * DD + c * 8);
        *(int4*)(sA + r * SPITCH + c * 8) = vv;
    }

    float acc[4][4][4];
    float rowpart[8];
    float cp[8];
#pragma unroll
    for (int k = 0; k < 8; k++) { rowpart[k] = 0.f; cp[k] = 0.f; }

    int g8 = lane & 7, q = lane >> 3;
    int g4 = lane >> 2, c2 = (lane & 3) * 2;
    uint32_t sA_u = smem_u32(sA);
    uint32_t sB_u = smem_u32(sB);

    for (int chunk = 0; chunk < 4; chunk++) {
        __syncthreads();  // protect sB from previous chunk's readers
        const __nv_bfloat16* rsrc = right + ((size_t)p * BB + chunk * 128) * DD;
        for (int i = tid; i < 128 * 32; i += 256) {
            int r = i >> 5, c = i & 31;
            const int4 vv = *(const int4*)(rsrc + (size_t)r * DD + c * 8);
            *(int4*)(sB + r * SPITCH + c * 8) = vv;
        }
        __syncthreads();
#pragma unroll
        for (int mt = 0; mt < 4; mt++)
#pragma unroll
            for (int nt = 0; nt < 4; nt++)
#pragma unroll
                for (int e = 0; e < 4; e++) acc[mt][nt][e] = 0.f;

        for (int kk = 0; kk < DD; kk += 16) {
            uint32_t a[4][4], bfr[4][2];
#pragma unroll
            for (int mt = 0; mt < 4; mt++) {
                int ar = warpM * 64 + mt * 16 + g8 + ((q & 1) ? 8 : 0);
                int ac = kk + ((q & 2) ? 8 : 0);
                ldsm_x4(a[mt][0], a[mt][1], a[mt][2], a[mt][3],
                        sA_u + (uint32_t)(ar * SPITCH + ac) * 2u);
            }
#pragma unroll
            for (int pr = 0; pr < 2; pr++) {
                int nb = warpN * 32 + pr * 16 + ((q & 2) ? 8 : 0) + g8;
                int bc = kk + ((q & 1) ? 8 : 0);
                ldsm_x4(bfr[2 * pr][0], bfr[2 * pr][1], bfr[2 * pr + 1][0],
                        bfr[2 * pr + 1][1], sB_u + (uint32_t)(nb * SPITCH + bc) * 2u);
            }
#pragma unroll
            for (int mt = 0; mt < 4; mt++)
#pragma unroll
                for (int nt = 0; nt < 4; nt++) mma16816(acc[mt][nt], a[mt], bfr[nt]);
        }

        // epilogue: sim = 2*dot ; exp ; diag exclusion for A and C ; row/col sums
        bool excl = (mat != 1) && (strip == chunk);
#pragma unroll
        for (int mt = 0; mt < 4; mt++) {
            int row_lo = warpM * 64 + mt * 16 + g4;
#pragma unroll
            for (int nt = 0; nt < 4; nt++) {
                int col = warpN * 32 + nt * 8 + c2;
                float e0 = __expf(2.f * acc[mt][nt][0]);
                float e1 = __expf(2.f * acc[mt][nt][1]);
                float e2 = __expf(2.f * acc[mt][nt][2]);
                float e3 = __expf(2.f * acc[mt][nt][3]);
                if (excl) {
                    if (row_lo == col) e0 = 0.f;
                    if (row_lo == col + 1) e1 = 0.f;
                    if (row_lo + 8 == col) e2 = 0.f;
                    if (row_lo + 8 == col + 1) e3 = 0.f;
                }
                rowpart[2 * mt] += e0 + e1;
                rowpart[2 * mt + 1] += e2 + e3;
                if (mat == 1) {
                    cp[2 * nt] += e0 + e2;
                    cp[2 * nt + 1] += e1 + e3;
                }
            }
        }
        if (mat == 1) {
#pragma unroll
            for (int k = 0; k < 8; k++) {
                cp[k] += __shfl_xor_sync(0xffffffffu, cp[k], 4);
                cp[k] += __shfl_xor_sync(0xffffffffu, cp[k], 8);
                cp[k] += __shfl_xor_sync(0xffffffffu, cp[k], 16);
            }
            if (lane < 4) {
#pragma unroll
                for (int nt = 0; nt < 4; nt++) {
                    int col = chunk * 128 + warpN * 32 + nt * 8 + lane * 2;
                    atomicAdd(&colsum_s[col], cp[2 * nt]);
                    atomicAdd(&colsum_s[col + 1], cp[2 * nt + 1]);
                }
            }
#pragma unroll
            for (int k = 0; k < 8; k++) cp[k] = 0.f;
        }
    }

    // flush row sums
#pragma unroll
    for (int k = 0; k < 8; k++) {
        rowpart[k] += __shfl_xor_sync(0xffffffffu, rowpart[k], 1);
        rowpart[k] += __shfl_xor_sync(0xffffffffu, rowpart[k], 2);
    }
    if ((lane & 3) == 0) {
#pragma unroll
        for (int mt = 0; mt < 4; mt++) {
            atomicAdd(&rowsum_s[warpM * 64 + mt * 16 + g4], rowpart[2 * mt]);
            atomicAdd(&rowsum_s[warpM * 64 + mt * 16 + g4 + 8], rowpart[2 * mt + 1]);
        }
    }
    __syncthreads();
    float* rdst = (mat == 0) ? rowA_g : (mat == 1 ? rowB_g : rowC_g);
    if (tid < 128) rdst[(size_t)p * BB + strip * 128 + tid] = rowsum_s[tid];
    if (mat == 1) {
        colB_g[((size_t)p * 4 + strip) * BB + tid] = colsum_s[tid];
        colB_g[((size_t)p * 4 + strip) * BB + tid + 256] = colsum_s[tid + 256];
    }
}

// ---------------- kernel 6: per-position loss ----------------
__global__ void finalize1_kernel() {
    __shared__ float red[16];
    int p = blockIdx.x, tid = threadIdx.x;
    size_t base = (size_t)p * BB + tid;
    float stop = rowA_g[base] + rowB_g[base];
    float sbot = rowC_g[base] + colB_g[((size_t)p * 4 + 0) * BB + tid] +
                 colB_g[((size_t)p * 4 + 1) * BB + tid] +
                 colB_g[((size_t)p * 4 + 2) * BB + tid] +
                 colB_g[((size_t)p * 4 + 3) * BB + tid];
    float v = 2.f * d_pos[base] - logf(stop) - logf(sbot);
    int lane = tid & 31, warp = tid >> 5;
#pragma unroll
    for (int s = 16; s > 0; s >>= 1) v += __shfl_xor_sync(0xffffffffu, v, s);
    if (lane == 0) red[warp] = v;
    __syncthreads();
    if (warp == 0) {
        v = (lane < 16) ? red[lane] : 0.f;
#pragma unroll
        for (int s = 8; s > 0; s >>= 1) v += __shfl_xor_sync(0xffffffffu, v, s);
        if (lane == 0) part_g[p] = -w_g[p] * v * (1.f / 1024.f);
    }
}

// ---------------- kernel 7: final sum ----------------
__global__ void finalize2_kernel(float* __restrict__ out) {
    __shared__ float red[8];
    int tid = threadIdx.x;
    float v = (tid < PP) ? part_g[tid] : 0.f;
    int lane = tid & 31, warp = tid >> 5;
#pragma unroll
    for (int s = 16; s > 0; s >>= 1) v += __shfl_xor_sync(0xffffffffu, v, s);
    if (lane == 0) red[warp] = v;
    __syncthreads();
    if (warp == 0) {
        v = (lane < 8) ? red[lane] : 0.f;
#pragma unroll
        for (int s = 4; s > 0; s >>= 1) v += __shfl_xor_sync(0xffffffffu, v, s);
        if (lane == 0) out[0] = v;
    }
}

// ---------------- launch ----------------
extern "C" void kernel_launch(void* const* d_in, const int* in_sizes, int n_in,
                              void* d_out, int out_size) {
    const float* gf = (const float*)d_in[0];    // global_feature [512,256]
    const float* att = (const float*)d_in[1];   // att [512,8,14,14]
    const float* outp = (const float*)d_in[2];  // outputs [512,256,14,14]
    float* out = (float*)d_out;

    const int smem_bytes = 2 * 128 * SPITCH * 2;
    cudaFuncSetAttribute(gemm_kernel, cudaFuncAttributeMaxDynamicSharedMemorySize,
                         smem_bytes);

    g_chain_kernel<<<64, 256>>>(gf);
    transpose_kernel<<<dim3(7, 8, 512), dim3(32, 8)>>>(outp);
    lf_prep_kernel<<<dim3(PP, 64), 256>>>();
    wmean_kernel<<<PP, 256>>>(att);
    gemm_kernel<<<dim3(4, 3, PP), 256, smem_bytes>>>();
    finalize1_kernel<<<PP, 512>>>();
    finalize2_kernel<<<1, 256>>>(out);
}

// round 2
// speedup vs baseline: 2.7760x; 2.7760x over previous
#include <cuda_runtime.h>
#include <cuda_bf16.h>
#include <cstdint>

#define BB 512
#define DD 256
#define PP 196
#define P0 8          // positions computed exactly; p>=P0 uses analytic uniform-G path
#define NCA 8
#define SPITCH 264    // padded bf16 row pitch (528B) -> conflict-free ldmatrix

// ---------------- scratch (static device arrays; no allocation) ----------------
__device__ __nv_bfloat16 g_hat[(size_t)P0 * BB * DD];   // normalized softmax^p(g), p<P0
__device__ __nv_bfloat16 lf_hat[(size_t)PP * BB * DD];  // normalized softmax(local)
__device__ float outT[(size_t)PP * BB * DD];            // outputs transposed [p][b][d]
__device__ float d_pos[(size_t)PP * BB];                // sim value of the positive pair
__device__ float rowA_g[(size_t)PP * BB];               // zeroed per launch, atomically built
__device__ float rowB_g[(size_t)P0 * BB];
__device__ float rowC_g[(size_t)P0 * BB];
__device__ float colB_g[(size_t)P0 * BB];
__device__ float w_g[PP];
__device__ float part_g[PP];

__device__ const int TAB_S[10] = {0, 0, 0, 0, 1, 1, 1, 2, 2, 3};
__device__ const int TAB_C[10] = {0, 1, 2, 3, 1, 2, 3, 2, 3, 3};

// ---------------- helpers ----------------
__device__ __forceinline__ uint32_t smem_u32(const void* p) {
    return (uint32_t)__cvta_generic_to_shared(p);
}
__device__ __forceinline__ void ldsm_x4(uint32_t& r0, uint32_t& r1, uint32_t& r2,
                                        uint32_t& r3, uint32_t addr) {
    asm volatile("ldmatrix.sync.aligned.m8n8.x4.shared.b16 {%0,%1,%2,%3}, [%4];\n"
                 : "=r"(r0), "=r"(r1), "=r"(r2), "=r"(r3)
                 : "r"(addr));
}
__device__ __forceinline__ void mma16816(float* c, const uint32_t* a, const uint32_t* b) {
    asm volatile(
        "mma.sync.aligned.m16n8k16.row.col.f32.bf16.bf16.f32 "
        "{%0,%1,%2,%3}, {%4,%5,%6,%7}, {%8,%9}, {%0,%1,%2,%3};\n"
        : "+f"(c[0]), "+f"(c[1]), "+f"(c[2]), "+f"(c[3])
        : "r"(a[0]), "r"(a[1]), "r"(a[2]), "r"(a[3]), "r"(b[0]), "r"(b[1]));
}
__device__ __forceinline__ void cp16(uint32_t dst, const void* src) {
    asm volatile("cp.async.cg.shared.global [%0], [%1], 16;\n" ::"r"(dst), "l"(src));
}
__device__ __forceinline__ void cp_commit_wait_all() {
    asm volatile("cp.async.commit_group;\ncp.async.wait_group 0;\n" ::: "memory");
}

// ---------------- kernel 1: repeated-softmax chain (only P0 steps needed) ----------------
__global__ void g_chain_kernel(const float* __restrict__ g0) {
    int warp = threadIdx.x >> 5, lane = threadIdx.x & 31;
    int b = blockIdx.x * 8 + warp;
    float v[8];
#pragma unroll
    for (int r = 0; r < 8; r++) v[r] = g0[b * DD + r * 32 + lane];
    for (int p = 0; p < P0; p++) {
        float m = v[0];
#pragma unroll
        for (int r = 1; r < 8; r++) m = fmaxf(m, v[r]);
#pragma unroll
        for (int s = 16; s > 0; s >>= 1) m = fmaxf(m, __shfl_xor_sync(0xffffffffu, m, s));
        float s = 0.f;
#pragma unroll
        for (int r = 0; r < 8; r++) { v[r] = __expf(v[r] - m); s += v[r]; }
#pragma unroll
        for (int t = 16; t > 0; t >>= 1) s += __shfl_xor_sync(0xffffffffu, s, t);
        float inv = 1.f / s;
        float sq = 0.f;
#pragma unroll
        for (int r = 0; r < 8; r++) { v[r] *= inv; sq += v[r] * v[r]; }
#pragma unroll
        for (int t = 16; t > 0; t >>= 1) sq += __shfl_xor_sync(0xffffffffu, sq, t);
        float sc = 1.f / (sqrtf(sq) + 1e-8f);
        __nv_bfloat16* dst = &g_hat[((size_t)p * BB + b) * DD];
#pragma unroll
        for (int r = 0; r < 8; r++) dst[r * 32 + lane] = __float2bfloat16(v[r] * sc);
    }
}

// ---------------- kernel 2: transpose outputs [b][d][p] -> outT [p][b][d] ----------------
__global__ void transpose_kernel(const float* __restrict__ outp) {
    __shared__ float tile[32][33];
    int b = blockIdx.z;
    int p0 = blockIdx.x * 32, d0 = blockIdx.y * 32;
    int tx = threadIdx.x, ty = threadIdx.y;
#pragma unroll
    for (int yy = ty; yy < 32; yy += 8) {
        int p = p0 + tx;
        if (p < PP) tile[yy][tx] = outp[((size_t)b * DD + d0 + yy) * PP + p];
    }
    __syncthreads();
#pragma unroll
    for (int yy = ty; yy < 32; yy += 8) {
        int p = p0 + yy;
        if (p < PP) outT[((size_t)p * BB + b) * DD + d0 + tx] = tile[tx][yy];
    }
}

// ---------------- kernel 3: local softmax + normalize + positive dot ----------------
__global__ void lf_prep_kernel() {
    int warp = threadIdx.x >> 5, lane = threadIdx.x & 31;
    int p = blockIdx.x;
    int b = blockIdx.y * 8 + warp;
    const float* src = &outT[((size_t)p * BB + b) * DD];
    float v[8];
#pragma unroll
    for (int r = 0; r < 8; r++) v[r] = src[r * 32 + lane];
    float m = v[0];
#pragma unroll
    for (int r = 1; r < 8; r++) m = fmaxf(m, v[r]);
#pragma unroll
    for (int s = 16; s > 0; s >>= 1) m = fmaxf(m, __shfl_xor_sync(0xffffffffu, m, s));
    float s = 0.f;
#pragma unroll
    for (int r = 0; r < 8; r++) { v[r] = __expf(v[r] - m); s += v[r]; }
#pragma unroll
    for (int t = 16; t > 0; t >>= 1) s += __shfl_xor_sync(0xffffffffu, s, t);
    float inv = 1.f / s;
    float sq = 0.f;
#pragma unroll
    for (int r = 0; r < 8; r++) { v[r] *= inv; sq += v[r] * v[r]; }
#pragma unroll
    for (int t = 16; t > 0; t >>= 1) sq += __shfl_xor_sync(0xffffffffu, sq, t);
    float sc = 1.f / (sqrtf(sq) + 1e-8f);
    __nv_bfloat16* dst = &lf_hat[((size_t)p * BB + b) * DD];

    float dot = 0.f, ssum = 0.f;
    if (p < P0) {
        const __nv_bfloat16* gp = &g_hat[((size_t)p * BB + b) * DD];
#pragma unroll
        for (int r = 0; r < 8; r++) {
            float z = v[r] * sc;
            dst[r * 32 + lane] = __float2bfloat16(z);
            dot += z * __bfloat162float(gp[r * 32 + lane]);
        }
#pragma unroll
        for (int t = 16; t > 0; t >>= 1) dot += __shfl_xor_sync(0xffffffffu, dot, t);
    } else {
#pragma unroll
        for (int r = 0; r < 8; r++) {
            float z = v[r] * sc;
            dst[r * 32 + lane] = __float2bfloat16(z);
            ssum += z;
        }
#pragma unroll
        for (int t = 16; t > 0; t >>= 1) ssum += __shfl_xor_sync(0xffffffffu, ssum, t);
        dot = ssum * (1.f / 16.f);  // X_i . uniform-unit-G
    }
    if (lane == 0) d_pos[(size_t)p * BB + b] = 2.f * dot;  // sim of positive pair
}

// ---------------- kernel 4: attention sums (coalesced) ----------------
__global__ void wsum_kernel(const float* __restrict__ att) {
    __shared__ float bins[PP];
    int tid = threadIdx.x;
    if (tid < PP) bins[tid] = 0.f;
    __syncthreads();
    int base = blockIdx.x * 1024;
#pragma unroll
    for (int e = 0; e < 4; e++) {
        int idx = base + e * 256 + tid;
        atomicAdd(&bins[idx % PP], att[idx]);
    }
    __syncthreads();
    if (tid < PP) atomicAdd(&w_g[tid], bins[tid]);
}

// ---------------- kernel 5: fused bf16 MMA Gram + exp row/col sums ----------------
// grid (16, mat=3, p=196); block 256 threads; each active block: 128x128x256.
// mat 0: A=X.X^T (all p, upper blocks only, symmetric credit)
// mat 1: B=X.G^T (p<P0, all 16 blocks, row+col sums)
// mat 2: C=G.G^T (p<P0, upper blocks only)
__global__ void __launch_bounds__(256, 1) gemm_kernel() {
    int x = blockIdx.x, mat = blockIdx.y, p = blockIdx.z;
    if (mat != 0 && p >= P0) return;
    int s, c;
    if (mat == 1) { s = x >> 2; c = x & 3; }
    else { if (x >= 10) return; s = TAB_S[x]; c = TAB_C[x]; }

    extern __shared__ __align__(16) __nv_bfloat16 smem[];
    __nv_bfloat16* sA = smem;                 // 128 x SPITCH
    __nv_bfloat16* sB = smem + 128 * SPITCH;  // 128 x SPITCH
    __shared__ float rowsum_s[128];
    __shared__ float colsum_s[128];

    int tid = threadIdx.x, lane = tid & 31, warp = tid >> 5;
    int warpM = warp & 1, warpN = warp >> 1;
    const __nv_bfloat16* L = (mat == 2) ? g_hat : lf_hat;
    const __nv_bfloat16* R = (mat == 0) ? lf_hat : g_hat;
    const __nv_bfloat16* lsrc = L + ((size_t)p * BB + s * 128) * DD;
    const __nv_bfloat16* rsrc = R + ((size_t)p * BB + c * 128) * DD;
    bool same = (mat != 1) && (s == c);
    bool docol = (mat == 1) || (c > s);

    if (tid < 128) { rowsum_s[tid] = 0.f; colsum_s[tid] = 0.f; }

    uint32_t sA_u = smem_u32(sA);
    uint32_t sB_u = same ? sA_u : smem_u32(sB);
    for (int i = tid; i < 128 * 32; i += 256) {
        int r = i >> 5, cs = i & 31;
        cp16(sA_u + (uint32_t)(r * SPITCH * 2 + cs * 16), lsrc + (size_t)r * DD + cs * 8);
    }
    if (!same) {
        for (int i = tid; i < 128 * 32; i += 256) {
            int r = i >> 5, cs = i & 31;
            cp16(sB_u + (uint32_t)(r * SPITCH * 2 + cs * 16), rsrc + (size_t)r * DD + cs * 8);
        }
    }
    cp_commit_wait_all();
    __syncthreads();

    float acc[4][4][4];
#pragma unroll
    for (int mt = 0; mt < 4; mt++)
#pragma unroll
        for (int nt = 0; nt < 4; nt++)
#pragma unroll
            for (int e = 0; e < 4; e++) acc[mt][nt][e] = 0.f;

    int g8 = lane & 7, q = lane >> 3;
    int g4 = lane >> 2, c2 = (lane & 3) * 2;

    for (int kk = 0; kk < DD; kk += 16) {
        uint32_t a[4][4], bfr[4][2];
#pragma unroll
        for (int mt = 0; mt < 4; mt++) {
            int ar = warpM * 64 + mt * 16 + g8 + ((q & 1) ? 8 : 0);
            int ac = kk + ((q & 2) ? 8 : 0);
            ldsm_x4(a[mt][0], a[mt][1], a[mt][2], a[mt][3],
                    sA_u + (uint32_t)(ar * SPITCH + ac) * 2u);
        }
#pragma unroll
        for (int pr = 0; pr < 2; pr++) {
            int nb = warpN * 32 + pr * 16 + ((q & 2) ? 8 : 0) + g8;
            int bc = kk + ((q & 1) ? 8 : 0);
            ldsm_x4(bfr[2 * pr][0], bfr[2 * pr][1], bfr[2 * pr + 1][0],
                    bfr[2 * pr + 1][1], sB_u + (uint32_t)(nb * SPITCH + bc) * 2u);
        }
#pragma unroll
        for (int mt = 0; mt < 4; mt++)
#pragma unroll
            for (int nt = 0; nt < 4; nt++) mma16816(acc[mt][nt], a[mt], bfr[nt]);
    }

    // epilogue: e = exp(2*dot); exclude diagonal on diag blocks of A/C
    float rowpart[8], cp[8];
#pragma unroll
    for (int k = 0; k < 8; k++) { rowpart[k] = 0.f; cp[k] = 0.f; }
    bool excl = same;
#pragma unroll
    for (int mt = 0; mt < 4; mt++) {
        int row_lo = warpM * 64 + mt * 16 + g4;
#pragma unroll
        for (int nt = 0; nt < 4; nt++) {
            int col = warpN * 32 + nt * 8 + c2;
            float e0 = __expf(2.f * acc[mt][nt][0]);
            float e1 = __expf(2.f * acc[mt][nt][1]);
            float e2 = __expf(2.f * acc[mt][nt][2]);
            float e3 = __expf(2.f * acc[mt][nt][3]);
            if (excl) {
                if (row_lo == col) e0 = 0.f;
                if (row_lo == col + 1) e1 = 0.f;
                if (row_lo + 8 == col) e2 = 0.f;
                if (row_lo + 8 == col + 1) e3 = 0.f;
            }
            rowpart[2 * mt] += e0 + e1;
            rowpart[2 * mt + 1] += e2 + e3;
            if (docol) {
                cp[2 * nt] += e0 + e2;
                cp[2 * nt + 1] += e1 + e3;
            }
        }
    }
    // row sums: reduce over lanes sharing g4 (stride 1,2)
#pragma unroll
    for (int k = 0; k < 8; k++) {
        rowpart[k] += __shfl_xor_sync(0xffffffffu, rowpart[k], 1);
        rowpart[k] += __shfl_xor_sync(0xffffffffu, rowpart[k], 2);
    }
    if ((lane & 3) == 0) {
#pragma unroll
        for (int mt = 0; mt < 4; mt++) {
            atomicAdd(&rowsum_s[warpM * 64 + mt * 16 + g4], rowpart[2 * mt]);
            atomicAdd(&rowsum_s[warpM * 64 + mt * 16 + g4 + 8], rowpart[2 * mt + 1]);
        }
    }
    if (docol) {
#pragma unroll
        for (int k = 0; k < 8; k++) {
            cp[k] += __shfl_xor_sync(0xffffffffu, cp[k], 4);
            cp[k] += __shfl_xor_sync(0xffffffffu, cp[k], 8);
            cp[k] += __shfl_xor_sync(0xffffffffu, cp[k], 16);
        }
        if (lane < 4) {
#pragma unroll
            for (int nt = 0; nt < 4; nt++) {
                int col = warpN * 32 + nt * 8 + lane * 2;
                atomicAdd(&colsum_s[col], cp[2 * nt]);
                atomicAdd(&colsum_s[col + 1], cp[2 * nt + 1]);
            }
        }
    }
    __syncthreads();

    float* rdst = (mat == 0) ? rowA_g : (mat == 1 ? rowB_g : rowC_g);
    if (tid < 128) atomicAdd(&rdst[(size_t)p * BB + s * 128 + tid], rowsum_s[tid]);
    if (docol && tid >= 128) {
        int j = tid - 128;
        float* cdst = (mat == 1) ? &colB_g[(size_t)p * BB + c * 128 + j]
                                 : &rdst[(size_t)p * BB + c * 128 + j];
        atomicAdd(cdst, colsum_s[j]);
    }
}

// ---------------- kernel 6: per-position loss ----------------
__global__ void finalize1_kernel() {
    __shared__ float red[16];
    __shared__ float Tsh;
    int p = blockIdx.x, tid = threadIdx.x;
    int lane = tid & 31, warp = tid >> 5;
    size_t base = (size_t)p * BB + tid;
    float dp = d_pos[base];
    float rA = rowA_g[base];
    float stop, sbot;
    if (p < P0) {
        stop = rA + rowB_g[base];
        sbot = rowC_g[base] + colB_g[base];
    } else {
        float e = __expf(dp);
        float t = e;
#pragma unroll
        for (int s = 16; s > 0; s >>= 1) t += __shfl_xor_sync(0xffffffffu, t, s);
        if (lane == 0) red[warp] = t;
        __syncthreads();
        if (warp == 0) {
            t = red[lane & 15];
#pragma unroll
            for (int s = 8; s > 0; s >>= 1) t += __shfl_xor_sync(0xffffffffu, t, s);
            if (lane == 0) Tsh = t;
        }
        __syncthreads();
        stop = rA + 512.f * e;
        sbot = Tsh + 511.f * 7.3890560989306495f;  // 511*e^2
        __syncthreads();
    }
    float v = 2.f * dp - logf(stop) - logf(sbot);
#pragma unroll
    for (int s = 16; s > 0; s >>= 1) v += __shfl_xor_sync(0xffffffffu, v, s);
    if (lane == 0) red[warp] = v;
    __syncthreads();
    if (warp == 0) {
        v = red[lane & 15];
#pragma unroll
        for (int s = 8; s > 0; s >>= 1) v += __shfl_xor_sync(0xffffffffu, v, s);
        if (lane == 0)
            part_g[p] = -w_g[p] * (1.f / (512.f * 196.f)) * v * (1.f / 1024.f);
    }
}

// ---------------- kernel 7: final sum ----------------
__global__ void finalize2_kernel(float* __restrict__ out) {
    __shared__ float red[8];
    int tid = threadIdx.x;
    float v = (tid < PP) ? part_g[tid] : 0.f;
    int lane = tid & 31, warp = tid >> 5;
#pragma unroll
    for (int s = 16; s > 0; s >>= 1) v += __shfl_xor_sync(0xffffffffu, v, s);
    if (lane == 0) red[warp] = v;
    __syncthreads();
    if (warp == 0) {
        v = (lane < 8) ? red[lane] : 0.f;
#pragma unroll
        for (int s = 4; s > 0; s >>= 1) v += __shfl_xor_sync(0xffffffffu, v, s);
        if (lane == 0) out[0] = v;
    }
}

// ---------------- launch ----------------
extern "C" void kernel_launch(void* const* d_in, const int* in_sizes, int n_in,
                              void* d_out, int out_size) {
    const float* gf = (const float*)d_in[0];    // global_feature [512,256]
    const float* att = (const float*)d_in[1];   // att [512,8,14,14]
    const float* outp = (const float*)d_in[2];  // outputs [512,256,14,14]
    float* out = (float*)d_out;

    const int smem_bytes = 2 * 128 * SPITCH * 2;
    cudaFuncSetAttribute(gemm_kernel, cudaFuncAttributeMaxDynamicSharedMemorySize,
                         smem_bytes);

    // zero the atomically-accumulated scratch (graph-capturable memsets)
    void *pA, *pB, *pC, *pCol, *pW;
    cudaGetSymbolAddress(&pA, rowA_g);
    cudaGetSymbolAddress(&pB, rowB_g);
    cudaGetSymbolAddress(&pC, rowC_g);
    cudaGetSymbolAddress(&pCol, colB_g);
    cudaGetSymbolAddress(&pW, w_g);
    cudaMemsetAsync(pA, 0, (size_t)PP * BB * sizeof(float));
    cudaMemsetAsync(pB, 0, (size_t)P0 * BB * sizeof(float));
    cudaMemsetAsync(pC, 0, (size_t)P0 * BB * sizeof(float));
    cudaMemsetAsync(pCol, 0, (size_t)P0 * BB * sizeof(float));
    cudaMemsetAsync(pW, 0, PP * sizeof(float));

    g_chain_kernel<<<64, 256>>>(gf);
    transpose_kernel<<<dim3(7, 8, 512), dim3(32, 8)>>>(outp);
    lf_prep_kernel<<<dim3(PP, 64), 256>>>();
    wsum_kernel<<<784, 256>>>(att);  // 512*8*196 = 784*1024 elements
    gemm_kernel<<<dim3(16, 3, PP), 256, smem_bytes>>>();
    finalize1_kernel<<<PP, 512>>>();
    finalize2_kernel<<<1, 256>>>(out);
}